// round 1
// baseline (speedup 1.0000x reference)
#include <cuda_runtime.h>

#define XS    128
#define BATCH 8
#define MPTS  500000
#define GRID_ELEMS (BATCH * XS * XS * XS)   // 16,777,216 floats = 64 MiB

// Scratch grid (device global — no allocation in kernel_launch)
__device__ float g_grid[GRID_ELEMS];

// ---------------------------------------------------------------------------
// Kernel 1: zero the grid (vectorized) and the 16 output accumulators
// ---------------------------------------------------------------------------
__global__ void zero_kernel(float* __restrict__ d_out) {
    const int n4 = GRID_ELEMS / 4;
    int tid = blockIdx.x * blockDim.x + threadIdx.x;
    if (tid < n4) {
        reinterpret_cast<float4*>(g_grid)[tid] = make_float4(0.f, 0.f, 0.f, 0.f);
    }
    if (tid < 2 * BATCH) {
        d_out[tid] = 0.f;
    }
}

// ---------------------------------------------------------------------------
// Kernel 2: scatter-add. Each thread handles 4 consecutive points so the
// (B*M,3) int32 index stream is read as 3x int4 and values as float4
// (perfectly coalesced 128b loads). 4 atomics per thread into L2-resident grid.
// ---------------------------------------------------------------------------
__global__ void scatter_kernel(const int4*  __restrict__ idx4,
                               const float4* __restrict__ val4) {
    const int nquads = (BATCH * MPTS) / 4;          // 1,000,000
    int tid = blockIdx.x * blockDim.x + threadIdx.x;
    if (tid >= nquads) return;

    int b = tid / (MPTS / 4);                       // 4 pts per thread, same batch
    long base = (long)b << 21;                      // b * 128^3

    int4 a0 = idx4[3 * tid + 0];                    // i0 j0 k0 i1
    int4 a1 = idx4[3 * tid + 1];                    // j1 k1 i2 j2
    int4 a2 = idx4[3 * tid + 2];                    // k2 i3 j3 k3
    float4 v = val4[tid];

    atomicAdd(&g_grid[base + ((long)a0.x << 14) + (a0.y << 7) + a0.z], v.x);
    atomicAdd(&g_grid[base + ((long)a0.w << 14) + (a1.x << 7) + a1.y], v.y);
    atomicAdd(&g_grid[base + ((long)a1.z << 14) + (a1.w << 7) + a2.x], v.z);
    atomicAdd(&g_grid[base + ((long)a2.y << 14) + (a2.z << 7) + a2.w], v.w);
}

// ---------------------------------------------------------------------------
// Kernel 3: TV + MSE reduction. Each thread accumulates 8 voxels (strided by
// blockDim within a 2048-voxel block chunk, all in one batch), then warp-shfl
// + shared-memory block reduce, then 2 float atomics per block.
// out layout: out[b] = tv_b, out[BATCH + b] = mse_b   (shape (2, B))
// ---------------------------------------------------------------------------
__global__ void reduce_kernel(float* __restrict__ d_out) {
    const long base = (long)blockIdx.x * 2048;      // 2^21 per batch -> aligned
    float tv = 0.f, mse = 0.f;

    #pragma unroll
    for (int s = 0; s < 8; s++) {
        long v = base + s * 256 + threadIdx.x;
        int k = (int)(v & 127);
        int j = (int)((v >> 7) & 127);
        int i = (int)((v >> 14) & 127);
        float c = g_grid[v];
        if (i < XS - 1) { float d = g_grid[v + XS * XS] - c; tv += fabsf(d); mse += d * d; }
        if (j < XS - 1) { float d = g_grid[v + XS]      - c; tv += fabsf(d); mse += d * d; }
        if (k < XS - 1) { float d = g_grid[v + 1]       - c; tv += fabsf(d); mse += d * d; }
    }

    // warp reduce
    #pragma unroll
    for (int off = 16; off > 0; off >>= 1) {
        tv  += __shfl_down_sync(0xFFFFFFFFu, tv,  off);
        mse += __shfl_down_sync(0xFFFFFFFFu, mse, off);
    }

    __shared__ float stv[8], smse[8];
    int lane = threadIdx.x & 31;
    int w    = threadIdx.x >> 5;
    if (lane == 0) { stv[w] = tv; smse[w] = mse; }
    __syncthreads();

    if (w == 0) {
        tv  = (lane < 8) ? stv[lane]  : 0.f;
        mse = (lane < 8) ? smse[lane] : 0.f;
        #pragma unroll
        for (int off = 4; off > 0; off >>= 1) {
            tv  += __shfl_down_sync(0xFFFFFFFFu, tv,  off);
            mse += __shfl_down_sync(0xFFFFFFFFu, mse, off);
        }
        if (lane == 0) {
            int b = (int)(base >> 21);
            const float tv_norm  = 1.f / (float)(XS * XS * XS);               // /2097152
            const float mse_norm = 1.f / (float)(2 * XS * XS - 2 * XS);       // /32512
            atomicAdd(&d_out[b],         tv  * tv_norm);
            atomicAdd(&d_out[BATCH + b], mse * mse_norm);
        }
    }
}

// ---------------------------------------------------------------------------
extern "C" void kernel_launch(void* const* d_in, const int* in_sizes, int n_in,
                              void* d_out, int out_size) {
    const int*   indices = (const int*)d_in[0];    // (B, M, 3) int32
    const float* values  = (const float*)d_in[1];  // (B, M) float32
    // d_in[2] is xsize (scalar) — compile-time constant here
    float* out = (float*)d_out;                    // (2, B) float32

    // 1. zero grid + outputs
    {
        int n4 = GRID_ELEMS / 4;
        int threads = 256;
        int blocks = (n4 + threads - 1) / threads;
        zero_kernel<<<blocks, threads>>>(out);
    }
    // 2. scatter
    {
        int nquads = (BATCH * MPTS) / 4;
        int threads = 256;
        int blocks = (nquads + threads - 1) / threads;
        scatter_kernel<<<blocks, threads>>>((const int4*)indices,
                                            (const float4*)values);
    }
    // 3. reduce
    {
        int blocks = GRID_ELEMS / 2048;            // 8192
        reduce_kernel<<<blocks, 256>>>(out);
    }
}

// round 2
// speedup vs baseline: 1.0888x; 1.0888x over previous
#include <cuda_runtime.h>

#define XS    128
#define BATCH 8
#define MPTS  500000
#define NPLANES (BATCH * XS)                 // 1024
#define GRID_ELEMS (BATCH * XS * XS * XS)    // 16,777,216 floats = 64 MiB

// Scratch (device globals: zero-initialized at module load, no allocations)
__device__ float g_grid[GRID_ELEMS];
__device__ int   g_done[NPLANES];

// ---------------------------------------------------------------------------
// Kernel 1: scatter-add. 4 points/thread -> 3x int4 + 1x float4 coalesced
// loads, 4 RED.ADD per thread into the L2-resident grid.
// Block 0 also zeroes the 16 output accumulators (read later by reduce).
// ---------------------------------------------------------------------------
__global__ void scatter_kernel(const int4*   __restrict__ idx4,
                               const float4* __restrict__ val4,
                               float*        __restrict__ d_out) {
    if (blockIdx.x == 0 && threadIdx.x < 2 * BATCH) d_out[threadIdx.x] = 0.f;

    const int nquads = (BATCH * MPTS) / 4;          // 1,000,000
    int tid = blockIdx.x * blockDim.x + threadIdx.x;
    if (tid >= nquads) return;

    int b = tid / (MPTS / 4);                       // 4 pts/thread, same batch
    long base = (long)b << 21;                      // b * 128^3

    int4 a0 = idx4[3 * tid + 0];                    // i0 j0 k0 i1
    int4 a1 = idx4[3 * tid + 1];                    // j1 k1 i2 j2
    int4 a2 = idx4[3 * tid + 2];                    // k2 i3 j3 k3
    float4 v = val4[tid];

    atomicAdd(&g_grid[base + ((long)a0.x << 14) + (a0.y << 7) + a0.z], v.x);
    atomicAdd(&g_grid[base + ((long)a0.w << 14) + (a1.x << 7) + a1.y], v.y);
    atomicAdd(&g_grid[base + ((long)a1.z << 14) + (a1.w << 7) + a2.x], v.z);
    atomicAdd(&g_grid[base + ((long)a2.y << 14) + (a2.z << 7) + a2.w], v.w);
}

// ---------------------------------------------------------------------------
// Kernel 2: fused TV+MSE reduction + grid re-zero.
// Block = one (b,i) plane (128x128 = 4096 float4). Warp = one j-row.
//   k-diffs: in-register within float4 + __shfl_down (k=127 boundary == lane31)
//   j-diffs: float4 at f+32 (L1 reuse from sibling warp's center load)
//   i-diffs: float4 at f+4096 (next plane)
// Zero protocol: plane p is read by block p (center) and block p-1 (neighbor,
// unless i==0). Each block increments g_done for planes it read when finished;
// the reader that hits the target count zeroes that plane and resets g_done.
// Self-cleaning across graph replays; first call relies on zero-init globals.
// ---------------------------------------------------------------------------
__global__ void reduce_zero_kernel(float* __restrict__ d_out) {
    const int plane = blockIdx.x;                  // 0..1023
    const int b = plane >> 7;
    const int i = plane & 127;
    const long pb = (long)plane << 12;             // plane base, float4 units
    const float4* __restrict__ g4 = (const float4*)g_grid;
    const bool has_i = (i < XS - 1);

    float tv = 0.f, mse = 0.f;

    #pragma unroll 4
    for (int it = 0; it < 16; ++it) {
        int f = it * 256 + threadIdx.x;            // 0..4095 (warp = 32 consec)
        float4 c = g4[pb + f];

        // k-direction: 3 internal diffs + one across lanes via shfl
        float nx = __shfl_down_sync(0xffffffffu, c.x, 1);
        {
            float d0 = c.y - c.x, d1 = c.z - c.y, d2 = c.w - c.z;
            tv  += fabsf(d0) + fabsf(d1) + fabsf(d2);
            mse += d0 * d0 + d1 * d1 + d2 * d2;
            if ((f & 31) != 31) {                  // k=127 boundary == lane 31
                float d3 = nx - c.w;
                tv += fabsf(d3); mse += d3 * d3;
            }
        }
        // j-direction (warp-uniform predicate: 4064 = 127*32)
        if (f < (XS - 1) * 32) {
            float4 jn = g4[pb + f + 32];
            float d0 = jn.x - c.x, d1 = jn.y - c.y, d2 = jn.z - c.z, d3 = jn.w - c.w;
            tv  += fabsf(d0) + fabsf(d1) + fabsf(d2) + fabsf(d3);
            mse += d0 * d0 + d1 * d1 + d2 * d2 + d3 * d3;
        }
        // i-direction (block-uniform predicate)
        if (has_i) {
            float4 in_ = g4[pb + 4096 + f];
            float d0 = in_.x - c.x, d1 = in_.y - c.y, d2 = in_.z - c.z, d3 = in_.w - c.w;
            tv  += fabsf(d0) + fabsf(d1) + fabsf(d2) + fabsf(d3);
            mse += d0 * d0 + d1 * d1 + d2 * d2 + d3 * d3;
        }
    }

    // warp reduce
    #pragma unroll
    for (int off = 16; off > 0; off >>= 1) {
        tv  += __shfl_down_sync(0xffffffffu, tv,  off);
        mse += __shfl_down_sync(0xffffffffu, mse, off);
    }
    __shared__ float stv[8], smse[8];
    int lane = threadIdx.x & 31;
    int w    = threadIdx.x >> 5;
    if (lane == 0) { stv[w] = tv; smse[w] = mse; }
    __syncthreads();
    if (w == 0 && lane == 0) {
        float ttv = 0.f, tmse = 0.f;
        #pragma unroll
        for (int s = 0; s < 8; s++) { ttv += stv[s]; tmse += smse[s]; }
        const float tv_norm  = 1.f / (float)(XS * XS * XS);
        const float mse_norm = 1.f / (float)(2 * XS * XS - 2 * XS);
        atomicAdd(&d_out[b],         ttv  * tv_norm);
        atomicAdd(&d_out[BATCH + b], tmse * mse_norm);
    }

    // ---- zero protocol ----
    __shared__ int zmask;
    if (threadIdx.x == 0) zmask = 0;
    __syncthreads();                                // all reads of this block done
    if (threadIdx.x == 0) {
        __threadfence();                            // release: reads retired
        int m = 0;
        int tgt = (i == 0) ? 1 : 2;
        if (atomicAdd(&g_done[plane], 1) + 1 == tgt) m |= 1;
        if (has_i) {
            if (atomicAdd(&g_done[plane + 1], 1) + 1 == 2) m |= 2;
        }
        zmask = m;
    }
    __syncthreads();
    int m = zmask;
    float4* gw = (float4*)g_grid;
    const float4 z = make_float4(0.f, 0.f, 0.f, 0.f);
    if (m & 1) {
        #pragma unroll
        for (int it = 0; it < 16; ++it)
            gw[pb + it * 256 + threadIdx.x] = z;
        if (threadIdx.x == 0) g_done[plane] = 0;
    }
    if (m & 2) {
        #pragma unroll
        for (int it = 0; it < 16; ++it)
            gw[pb + 4096 + it * 256 + threadIdx.x] = z;
        if (threadIdx.x == 0) g_done[plane + 1] = 0;
    }
}

// ---------------------------------------------------------------------------
extern "C" void kernel_launch(void* const* d_in, const int* in_sizes, int n_in,
                              void* d_out, int out_size) {
    const int*   indices = (const int*)d_in[0];    // (B, M, 3) int32
    const float* values  = (const float*)d_in[1];  // (B, M) float32
    float* out = (float*)d_out;                    // (2, B) float32

    {
        int nquads = (BATCH * MPTS) / 4;
        int threads = 256;
        int blocks = (nquads + threads - 1) / threads;
        scatter_kernel<<<blocks, threads>>>((const int4*)indices,
                                            (const float4*)values, out);
    }
    {
        reduce_zero_kernel<<<NPLANES, 256>>>(out);
    }
}